// round 7
// baseline (speedup 1.0000x reference)
#include <cuda_runtime.h>
#include <math.h>

#define DD    512
#define HH    256
#define G4    1024
#define NT    128
#define NB    5
#define NEP   1024
#define M640  640      // NT*NB
#define SCTA  64       // scan CTAs (32 per direction)

// ---------- static device scratch (no allocation) ----------
__device__ __align__(16) float g_v[DD];
__device__ float g_c0;
__device__ __align__(16) float g_scores[NEP];
__device__ int   g_idx[8];
__device__ float g_wsel[8];
__device__ __align__(16) float g_x0 [M640 * DD];       // scaled selected episodes [t][b][d]
__device__ __align__(16) float g_x1 [M640 * DD];       // layer-0 output
__device__ __align__(16) float g_lout[M640 * DD];      // layer-1 output
__device__ __align__(16) float g_pre[2 * M640 * G4];   // pre-gates [dir][m][j]
__device__ unsigned g_bar[512];                        // [phase][dir][step]

// ---------------- zero barriers ----------------
__global__ void k_zero() {
    int i = blockIdx.x * 256 + threadIdx.x;
    if (i < 512) g_bar[i] = 0u;
}

// ---------------- qp = Wq@q + bq ; v = Wk^T@qp ; c0 = bk.qp ----------------
__global__ void k_prep(const float* __restrict__ query, const float* __restrict__ Wq,
                       const float* __restrict__ bq, const float* __restrict__ Wk,
                       const float* __restrict__ bk) {
    __shared__ float qs[DD], qps[DD], red[DD];
    int tid = threadIdx.x;
    qs[tid] = query[tid];
    __syncthreads();
    const float* wr = Wq + (size_t)tid * DD;
    float s = bq[tid];
#pragma unroll 8
    for (int d = 0; d < DD; d++) s += wr[d] * qs[d];
    qps[tid] = s;
    __syncthreads();
    float vv = 0.f;
#pragma unroll 8
    for (int e = 0; e < DD; e++) vv += Wk[(size_t)e * DD + tid] * qps[e];
    g_v[tid] = vv;
    red[tid] = bk[tid] * qps[tid];
    __syncthreads();
    for (int st = 256; st > 0; st >>= 1) {
        if (tid < st) red[tid] += red[tid + st];
        __syncthreads();
    }
    if (tid == 0) g_c0 = red[0];
}

// ---------------- scores[n] = mean_l(ep[n][l]) . v + c0 ----------------
__global__ void k_scores(const float* __restrict__ ep) {
    __shared__ float4 vs[DD / 4];
    __shared__ float sred[256];
    int tid = threadIdx.x;
    if (tid < 128) vs[tid] = ((const float4*)g_v)[tid];
    __syncthreads();
    const float4* e4 = (const float4*)ep + (size_t)blockIdx.x * (NT * DD / 4);
    float acc = 0.f;
#pragma unroll 4
    for (int it = 0; it < 64; it++) {
        int i = tid + 256 * it;
        float4 x = e4[i];
        float4 w = vs[i & 127];
        acc += x.x * w.x + x.y * w.y + x.z * w.z + x.w * w.w;
    }
    sred[tid] = acc;
    __syncthreads();
    for (int st = 128; st > 0; st >>= 1) {
        if (tid < st) sred[tid] += sred[tid + st];
        __syncthreads();
    }
    if (tid == 0) g_scores[blockIdx.x] = sred[0] * (1.0f / NT) + g_c0;
}

// ---------------- iterative top-5 ----------------
__global__ void k_topk(const float* __restrict__ ages) {
    __shared__ float sc[NEP];
    __shared__ float rv[256];
    __shared__ int   ri[256];
    int tid = threadIdx.x;
    for (int i = tid; i < NEP; i += 256) sc[i] = g_scores[i];
    __syncthreads();
    for (int r = 0; r < NB; r++) {
        float bv = -INFINITY; int bi = 0x7fffffff;
        for (int i = tid; i < NEP; i += 256) {
            float v = sc[i];
            if (v > bv || (v == bv && i < bi)) { bv = v; bi = i; }
        }
        rv[tid] = bv; ri[tid] = bi;
        __syncthreads();
        for (int st = 128; st > 0; st >>= 1) {
            if (tid < st) {
                float ov = rv[tid + st]; int oi = ri[tid + st];
                if (ov > rv[tid] || (ov == rv[tid] && oi < ri[tid])) { rv[tid] = ov; ri[tid] = oi; }
            }
            __syncthreads();
        }
        if (tid == 0) {
            g_idx[r]  = ri[0];
            g_wsel[r] = 1.f / (1.f + ages[ri[0]] * 0.01f);
            sc[ri[0]] = -INFINITY;
        }
        __syncthreads();
    }
}

// ---------------- x0[t][b][d] = ep[idx[b]][t][d] * w[b] ----------------
__global__ void k_gather(const float* __restrict__ ep) {
    int t = blockIdx.x, b = blockIdx.y, tid = threadIdx.x;
    int n = g_idx[b];
    float wv = g_wsel[b];
    const float4* src = (const float4*)(ep + ((size_t)n * NT + t) * DD);
    float4* dst = (float4*)(g_x0 + ((size_t)t * NB + b) * DD);
    float4 x = src[tid];
    x.x *= wv; x.y *= wv; x.z *= wv; x.w *= wv;
    dst[tid] = x;
}

// ---------------- pre[dir][m][j] = X[m].Wih[j] + bi[j] + bh[j] ----------------
// grid (16 nt, 10 mt, 2 dir) x 256, 64x64x16 tiles
__global__ void __launch_bounds__(256) k_gemm(int phase,
        const float* __restrict__ B0, const float* __restrict__ bi0, const float* __restrict__ bh0,
        const float* __restrict__ B1, const float* __restrict__ bi1, const float* __restrict__ bh1) {
    const float* A = phase ? g_x1 : g_x0;
    int dir = blockIdx.z;
    const float* B  = dir ? B1  : B0;
    const float* bi = dir ? bi1 : bi0;
    const float* bh = dir ? bh1 : bh0;
    float* C = g_pre + (size_t)dir * M640 * G4;

    __shared__ __align__(16) float As[16][68];
    __shared__ __align__(16) float Bs[16][68];

    int tid = threadIdx.x;
    int m0 = blockIdx.y * 64, n0 = blockIdx.x * 64;
    int tx = tid & 15, ty = tid >> 4;
    float acc[4][4];
#pragma unroll
    for (int i = 0; i < 4; i++)
#pragma unroll
        for (int j = 0; j < 4; j++) acc[i][j] = 0.f;

    int ml = tid >> 2, kl = (tid & 3) << 2;
    const float* Ag = A + (size_t)(m0 + ml) * DD + kl;
    const float* Bg = B + (size_t)(n0 + ml) * DD + kl;

    for (int k0 = 0; k0 < DD; k0 += 16) {
        float4 av = *(const float4*)(Ag + k0);
        float4 bv = *(const float4*)(Bg + k0);
        As[kl + 0][ml] = av.x; As[kl + 1][ml] = av.y; As[kl + 2][ml] = av.z; As[kl + 3][ml] = av.w;
        Bs[kl + 0][ml] = bv.x; Bs[kl + 1][ml] = bv.y; Bs[kl + 2][ml] = bv.z; Bs[kl + 3][ml] = bv.w;
        __syncthreads();
#pragma unroll
        for (int kk = 0; kk < 16; kk++) {
            float4 a = *(const float4*)&As[kk][ty << 2];
            float4 b = *(const float4*)&Bs[kk][tx << 2];
            float aa[4] = { a.x, a.y, a.z, a.w };
            float bb[4] = { b.x, b.y, b.z, b.w };
#pragma unroll
            for (int i = 0; i < 4; i++)
#pragma unroll
                for (int j = 0; j < 4; j++) acc[i][j] += aa[i] * bb[j];
        }
        __syncthreads();
    }
#pragma unroll
    for (int i = 0; i < 4; i++) {
        int m = m0 + (ty << 2) + i;
        int n = n0 + (tx << 2);
        float4 o;
        o.x = acc[i][0] + bi[n + 0] + bh[n + 0];
        o.y = acc[i][1] + bi[n + 1] + bh[n + 1];
        o.z = acc[i][2] + bi[n + 2] + bh[n + 2];
        o.w = acc[i][3] + bi[n + 3] + bh[n + 3];
        *(float4*)&C[(size_t)m * G4 + n] = o;
    }
}

// ---------------- bidirectional LSTM scan (one layer phase) ----------------
// 64 persistent CTAs x 256 thr; CTA owns 8 hidden units (32 gate rows).
// Padded smem layout: e_pad = e + (e>>5)*4  (row length 288) => conflict-free f4.
__global__ void __launch_bounds__(256) k_scan(int phase,
        const float* __restrict__ whf, const float* __restrict__ whb) {
    float* out = phase ? g_lout : g_x1;
    int cta = blockIdx.x;
    int dir = cta >> 5;
    int gidx = cta & 31;
    int hbase = gidx * 8;
    const float* whh  = dir ? whb : whf;
    const float* preb = g_pre + (size_t)dir * M640 * G4;
    unsigned* bar = g_bar + (phase * 2 + dir) * 128;

    int tid = threadIdx.x;
    int r = tid >> 3, seg = tid & 7;           // matvec role: gate-row r, h-segment seg

    __shared__ __align__(16) float ws [32][288];   // padded w_hh slice
    __shared__ __align__(16) float hsp[NB][288];   // padded staged h
    __shared__ float red [32][8][NB];
    __shared__ float garr[32][NB];

    // preload weights (rows j = (r>>3)*256 + hbase + (r&7))
    for (int idx = tid; idx < 32 * 256; idx += 256) {
        int rr = idx >> 8, e = idx & 255;
        int j = (rr >> 3) * HH + hbase + (rr & 7);
        ws[rr][e + ((e >> 5) << 2)] = whh[(size_t)j * HH + e];
    }
    __syncthreads();

    // fixed roles
    int rr5 = tid / NB, b5 = tid - rr5 * NB;               // reduce role (tid<160)
    int jred = (rr5 >> 3) * HH + hbase + (rr5 & 7);
    int u8 = tid / NB, b8 = tid - u8 * NB;                 // activation role (tid<40)
    float cstate = 0.f;
    volatile const float* vout = out;

    for (int s = 0; s < NT; s++) {
        int t = dir ? (NT - 1 - s) : s;

        // prefetch pre-gate for this step (reduce threads)
        float prev = 0.f;
        if (tid < 32 * NB) prev = __ldg(&preb[((size_t)t * NB + b5) * G4 + jred]);

        float acc[NB] = {0.f, 0.f, 0.f, 0.f, 0.f};
        if (s > 0) {
#pragma unroll
            for (int i4 = 0; i4 < 8; i4++) {
                float4 w = *(const float4*)&ws[r][seg * 36 + (i4 << 2)];
#pragma unroll
                for (int b = 0; b < NB; b++) {
                    float4 h = *(const float4*)&hsp[b][seg * 36 + (i4 << 2)];
                    acc[b] += w.x * h.x + w.y * h.y + w.z * h.z + w.w * h.w;
                }
            }
        }
#pragma unroll
        for (int b = 0; b < NB; b++) red[r][seg][b] = acc[b];
        __syncthreads();

        if (tid < 32 * NB) {
            float ssum = prev;
#pragma unroll
            for (int q = 0; q < 8; q++) ssum += red[rr5][q][b5];
            garr[rr5][b5] = ssum;
        }
        __syncthreads();

        if (tid < 8 * NB) {
            float ig = garr[u8][b8];
            float fg = garr[8 + u8][b8];
            float cg = garr[16 + u8][b8];
            float og = garr[24 + u8][b8];
            float si = 1.f / (1.f + expf(-ig));
            float sf = 1.f / (1.f + expf(-fg));
            float so = 1.f / (1.f + expf(-og));
            cstate = sf * cstate + si * tanhf(cg);
            float hv = so * tanhf(cstate);
            out[((size_t)t * NB + b8) * DD + dir * HH + hbase + u8] = hv;
            __threadfence();
        }
        __syncthreads();

        if (s == NT - 1) break;

        if (tid == 0) {
            atomicAdd(&bar[s], 1u);
            while (((volatile unsigned*)bar)[s] < 32u) { }
        }
        __syncthreads();

        // stage h_t of own direction (L2 reads, bypass L1 via volatile)
        int epad = tid + ((tid >> 5) << 2);
#pragma unroll
        for (int b = 0; b < NB; b++)
            hsp[b][epad] = vout[((size_t)t * NB + b) * DD + dir * HH + tid];
        __syncthreads();
    }
}

// ---------------- attention + softmax + context ----------------
__global__ void k_attn(const float* __restrict__ cs, float* __restrict__ outp) {
    __shared__ __align__(16) float css[DD];
    __shared__ float aw[NT];
    __shared__ float r1[NT];
    int b = blockIdx.x, tid = threadIdx.x;
    ((float4*)css)[tid] = ((const float4*)cs)[tid];
    __syncthreads();

    const float4* lb = (const float4*)(g_lout + ((size_t)tid * NB + b) * DD);
    float att = 0.f;
#pragma unroll 4
    for (int i = 0; i < DD / 4; i++) {
        float4 x = lb[i];
        float4 c = ((float4*)css)[i];
        att += x.x * c.x + x.y * c.y + x.z * c.z + x.w * c.w;
    }
    r1[tid] = att;
    __syncthreads();
    for (int st = 64; st > 0; st >>= 1) {
        if (tid < st) r1[tid] = fmaxf(r1[tid], r1[tid + st]);
        __syncthreads();
    }
    float mx = r1[0];
    __syncthreads();
    float e = expf(att - mx);
    r1[tid] = e;
    __syncthreads();
    for (int st = 64; st > 0; st >>= 1) {
        if (tid < st) r1[tid] += r1[tid + st];
        __syncthreads();
    }
    float inv = 1.f / r1[0];
    __syncthreads();
    aw[tid] = e * inv;
    __syncthreads();

    float4 ctx = make_float4(0.f, 0.f, 0.f, 0.f);
    for (int l = 0; l < NT; l++) {
        float wv = aw[l];
        float4 x = *(const float4*)(g_lout + ((size_t)l * NB + b) * DD + (tid << 2));
        ctx.x += wv * x.x; ctx.y += wv * x.y; ctx.z += wv * x.z; ctx.w += wv * x.w;
    }
    *(float4*)(outp + (size_t)b * DD + (tid << 2)) = ctx;
}

// ---------------- launcher ----------------
extern "C" void kernel_launch(void* const* d_in, const int* in_sizes, int n_in,
                              void* d_out, int out_size) {
    const float* episodes = (const float*)d_in[0];
    const float* query    = (const float*)d_in[1];
    const float* cstate   = (const float*)d_in[2];
    const float* ages     = (const float*)d_in[3];
    const float* Wq = (const float*)d_in[4];
    const float* bq = (const float*)d_in[5];
    const float* Wk = (const float*)d_in[6];
    const float* bk = (const float*)d_in[7];
    const float* w_ih_l0  = (const float*)d_in[8];
    const float* w_hh_l0  = (const float*)d_in[9];
    const float* b_ih_l0  = (const float*)d_in[10];
    const float* b_hh_l0  = (const float*)d_in[11];
    const float* w_ih_l0r = (const float*)d_in[12];
    const float* w_hh_l0r = (const float*)d_in[13];
    const float* b_ih_l0r = (const float*)d_in[14];
    const float* b_hh_l0r = (const float*)d_in[15];
    const float* w_ih_l1  = (const float*)d_in[16];
    const float* w_hh_l1  = (const float*)d_in[17];
    const float* b_ih_l1  = (const float*)d_in[18];
    const float* b_hh_l1  = (const float*)d_in[19];
    const float* w_ih_l1r = (const float*)d_in[20];
    const float* w_hh_l1r = (const float*)d_in[21];
    const float* b_ih_l1r = (const float*)d_in[22];
    const float* b_hh_l1r = (const float*)d_in[23];
    float* out = (float*)d_out;

    k_zero  <<<2, 256>>>();
    k_prep  <<<1, 512>>>(query, Wq, bq, Wk, bk);
    k_scores<<<NEP, 256>>>(episodes);
    k_topk  <<<1, 256>>>(ages);
    k_gather<<<dim3(NT, NB), 128>>>(episodes);

    k_gemm<<<dim3(16, 10, 2), 256>>>(0, w_ih_l0, b_ih_l0, b_hh_l0,
                                        w_ih_l0r, b_ih_l0r, b_hh_l0r);
    k_scan<<<SCTA, 256>>>(0, w_hh_l0, w_hh_l0r);

    k_gemm<<<dim3(16, 10, 2), 256>>>(1, w_ih_l1, b_ih_l1, b_hh_l1,
                                        w_ih_l1r, b_ih_l1r, b_hh_l1r);
    k_scan<<<SCTA, 256>>>(1, w_hh_l1, w_hh_l1r);

    k_attn<<<NB, 128>>>(cstate, out);
}

// round 8
// speedup vs baseline: 1.1504x; 1.1504x over previous
#include <cuda_runtime.h>
#include <math.h>

#define DD    512
#define HH    256
#define G4    1024
#define NT    128
#define NB    5
#define NEP   1024
#define M640  640      // NT*NB
#define SCTA  64       // scan CTAs (32 per direction)

// ---------- static device scratch (no allocation) ----------
__device__ __align__(16) float g_v[DD];
__device__ float g_c0;
__device__ __align__(16) float g_scores[NEP];
__device__ int   g_idx[8];
__device__ float g_wsel[8];
__device__ __align__(16) float g_x0 [M640 * DD];       // scaled selected episodes [t][b][d]
__device__ __align__(16) float g_x1 [M640 * DD];       // layer-0 output
__device__ __align__(16) float g_lout[M640 * DD];      // layer-1 output
__device__ __align__(16) float g_pre[2 * M640 * G4];   // pre-gates [dir][m][j]
__device__ unsigned g_bar[512];                        // [phase][dir][step]

// ---------- packed fp32x2 FMA (Blackwell FFMA2, PTX-only) ----------
union F2U { float2 f; unsigned long long u; };
__device__ __forceinline__ float2 f2fma(float2 a, float2 b, float2 c) {
    F2U A, B, C, Dv; A.f = a; B.f = b; C.f = c;
    asm("fma.rn.f32x2 %0, %1, %2, %3;" : "=l"(Dv.u) : "l"(A.u), "l"(B.u), "l"(C.u));
    return Dv.f;
}

__device__ __forceinline__ float fast_tanh(float x) {
    float r;
    asm("tanh.approx.f32 %0, %1;" : "=f"(r) : "f"(x));
    return r;
}
__device__ __forceinline__ float fast_sigmoid(float x) {
    return __fdividef(1.f, 1.f + __expf(-x));
}

// ---------------- zero barriers ----------------
__global__ void k_zero() {
    int i = threadIdx.x;
    if (i < 512) g_bar[i] = 0u;
}

// ---------------- qp = Wq@q + bq ; v = Wk^T@qp ; c0 = bk.qp ----------------
__global__ void k_prep(const float* __restrict__ query, const float* __restrict__ Wq,
                       const float* __restrict__ bq, const float* __restrict__ Wk,
                       const float* __restrict__ bk) {
    __shared__ float qs[DD], qps[DD], red[DD];
    int tid = threadIdx.x;
    qs[tid] = query[tid];
    __syncthreads();
    const float* wr = Wq + (size_t)tid * DD;
    float s = bq[tid];
#pragma unroll 8
    for (int d = 0; d < DD; d++) s += wr[d] * qs[d];
    qps[tid] = s;
    __syncthreads();
    float vv = 0.f;
#pragma unroll 8
    for (int e = 0; e < DD; e++) vv += Wk[(size_t)e * DD + tid] * qps[e];
    g_v[tid] = vv;
    red[tid] = bk[tid] * qps[tid];
    __syncthreads();
    for (int st = 256; st > 0; st >>= 1) {
        if (tid < st) red[tid] += red[tid + st];
        __syncthreads();
    }
    if (tid == 0) g_c0 = red[0];
}

// ---------------- scores[n] = mean_l(ep[n][l]) . v + c0 ----------------
__global__ void k_scores(const float* __restrict__ ep) {
    __shared__ float4 vs[DD / 4];
    __shared__ float sred[256];
    int tid = threadIdx.x;
    if (tid < 128) vs[tid] = ((const float4*)g_v)[tid];
    __syncthreads();
    const float4* e4 = (const float4*)ep + (size_t)blockIdx.x * (NT * DD / 4);
    float acc = 0.f;
#pragma unroll 4
    for (int it = 0; it < 64; it++) {
        int i = tid + 256 * it;
        float4 x = e4[i];
        float4 w = vs[i & 127];
        acc += x.x * w.x + x.y * w.y + x.z * w.z + x.w * w.w;
    }
    sred[tid] = acc;
    __syncthreads();
    for (int st = 128; st > 0; st >>= 1) {
        if (tid < st) sred[tid] += sred[tid + st];
        __syncthreads();
    }
    if (tid == 0) g_scores[blockIdx.x] = sred[0] * (1.0f / NT) + g_c0;
}

// ---------------- iterative top-5 (1024 threads, 1 elem each) ----------------
__global__ void __launch_bounds__(1024) k_topk(const float* __restrict__ ages) {
    __shared__ float sc[NEP];
    __shared__ float rv[1024];
    __shared__ int   ri[1024];
    int tid = threadIdx.x;
    sc[tid] = g_scores[tid];
    __syncthreads();
    for (int r = 0; r < NB; r++) {
        rv[tid] = sc[tid]; ri[tid] = tid;
        __syncthreads();
        for (int st = 512; st > 0; st >>= 1) {
            if (tid < st) {
                float ov = rv[tid + st]; int oi = ri[tid + st];
                if (ov > rv[tid] || (ov == rv[tid] && oi < ri[tid])) { rv[tid] = ov; ri[tid] = oi; }
            }
            __syncthreads();
        }
        if (tid == 0) {
            g_idx[r]  = ri[0];
            g_wsel[r] = 1.f / (1.f + ages[ri[0]] * 0.01f);
            sc[ri[0]] = -INFINITY;
        }
        __syncthreads();
    }
}

// ---------------- x0[t][b][d] = ep[idx[b]][t][d] * w[b] ----------------
__global__ void k_gather(const float* __restrict__ ep) {
    int t = blockIdx.x, b = blockIdx.y, tid = threadIdx.x;
    int n = g_idx[b];
    float wv = g_wsel[b];
    const float4* src = (const float4*)(ep + ((size_t)n * NT + t) * DD);
    float4* dst = (float4*)(g_x0 + ((size_t)t * NB + b) * DD);
    float4 x = src[tid];
    x.x *= wv; x.y *= wv; x.z *= wv; x.w *= wv;
    dst[tid] = x;
}

// ---------------- pre[dir][m][j] = X[m].Wih[j] + bi[j] + bh[j] ----------------
// grid (16 nt, 10 mt, 2 dir) x 256, 64x64x16 tiles
__global__ void __launch_bounds__(256) k_gemm(int phase,
        const float* __restrict__ B0, const float* __restrict__ bi0, const float* __restrict__ bh0,
        const float* __restrict__ B1, const float* __restrict__ bi1, const float* __restrict__ bh1) {
    const float* A = phase ? g_x1 : g_x0;
    int dir = blockIdx.z;
    const float* B  = dir ? B1  : B0;
    const float* bi = dir ? bi1 : bi0;
    const float* bh = dir ? bh1 : bh0;
    float* C = g_pre + (size_t)dir * M640 * G4;

    __shared__ __align__(16) float As[16][68];
    __shared__ __align__(16) float Bs[16][68];

    int tid = threadIdx.x;
    int m0 = blockIdx.y * 64, n0 = blockIdx.x * 64;
    int tx = tid & 15, ty = tid >> 4;
    float acc[4][4];
#pragma unroll
    for (int i = 0; i < 4; i++)
#pragma unroll
        for (int j = 0; j < 4; j++) acc[i][j] = 0.f;

    int ml = tid >> 2, kl = (tid & 3) << 2;
    const float* Ag = A + (size_t)(m0 + ml) * DD + kl;
    const float* Bg = B + (size_t)(n0 + ml) * DD + kl;

    for (int k0 = 0; k0 < DD; k0 += 16) {
        float4 av = *(const float4*)(Ag + k0);
        float4 bv = *(const float4*)(Bg + k0);
        As[kl + 0][ml] = av.x; As[kl + 1][ml] = av.y; As[kl + 2][ml] = av.z; As[kl + 3][ml] = av.w;
        Bs[kl + 0][ml] = bv.x; Bs[kl + 1][ml] = bv.y; Bs[kl + 2][ml] = bv.z; Bs[kl + 3][ml] = bv.w;
        __syncthreads();
#pragma unroll
        for (int kk = 0; kk < 16; kk++) {
            float4 a = *(const float4*)&As[kk][ty << 2];
            float4 b = *(const float4*)&Bs[kk][tx << 2];
            float aa[4] = { a.x, a.y, a.z, a.w };
            float bb[4] = { b.x, b.y, b.z, b.w };
#pragma unroll
            for (int i = 0; i < 4; i++)
#pragma unroll
                for (int j = 0; j < 4; j++) acc[i][j] += aa[i] * bb[j];
        }
        __syncthreads();
    }
#pragma unroll
    for (int i = 0; i < 4; i++) {
        int m = m0 + (ty << 2) + i;
        int n = n0 + (tx << 2);
        float4 o;
        o.x = acc[i][0] + bi[n + 0] + bh[n + 0];
        o.y = acc[i][1] + bi[n + 1] + bh[n + 1];
        o.z = acc[i][2] + bi[n + 2] + bh[n + 2];
        o.w = acc[i][3] + bi[n + 3] + bh[n + 3];
        *(float4*)&C[(size_t)m * G4 + n] = o;
    }
}

// ---------------- bidirectional LSTM scan (one layer phase) ----------------
// 64 persistent CTAs x 256 thr; CTA owns 8 hidden units (32 gate rows).
// NEW layout: warp = h-segment (broadcast h reads), lane = gate row,
// w_hh slice in registers, f32x2 FMA, approx activations.
__global__ void __launch_bounds__(256) k_scan(int phase,
        const float* __restrict__ whf, const float* __restrict__ whb) {
    float* out = phase ? g_lout : g_x1;
    int cta = blockIdx.x;
    int dir = cta >> 5;
    int gidx = cta & 31;
    int hbase = gidx * 8;
    const float* whh  = dir ? whb : whf;
    const float* preb = g_pre + (size_t)dir * M640 * G4;
    unsigned* bar = g_bar + (phase * 2 + dir) * 128;

    int tid  = threadIdx.x;
    int wsg  = tid >> 5;     // h-segment 0..7: elements [wsg*32, wsg*32+32)
    int lane = tid & 31;     // gate row 0..31
    int jrow = (lane >> 3) * HH + hbase + (lane & 7);

    // weights into registers: this thread's 32 w_hh values as 16 float2
    float2 wreg[16];
    {
        const float2* wr = (const float2*)(whh + (size_t)jrow * HH + wsg * 32);
#pragma unroll
        for (int i = 0; i < 16; i++) wreg[i] = wr[i];
    }

    __shared__ __align__(16) float hsp[NB][HH];  // staged h_{t-1}
    __shared__ float red [8][32][NB];            // per-segment partials
    __shared__ float garr[32][NB];               // reduced gate pre-acts

    int rr5 = tid / NB, b5 = tid - rr5 * NB;              // reduce role (tid<160)
    int jred = (rr5 >> 3) * HH + hbase + (rr5 & 7);
    int u8 = tid / NB, b8 = tid - u8 * NB;                // activation role (tid<40)
    float cstate = 0.f;
    volatile const float* vout = out;

    for (int s = 0; s < NT; s++) {
        int t = dir ? (NT - 1 - s) : s;

        // prefetch pre-gate for this step (overlaps matvec)
        float prev = 0.f;
        if (tid < 32 * NB) prev = __ldg(&preb[((size_t)t * NB + b5) * G4 + jred]);

        float2 acc[NB];
#pragma unroll
        for (int b = 0; b < NB; b++) acc[b] = make_float2(0.f, 0.f);
        if (s > 0) {
#pragma unroll
            for (int i4 = 0; i4 < 8; i4++) {
                float2 w0 = wreg[2 * i4], w1 = wreg[2 * i4 + 1];
#pragma unroll
                for (int b = 0; b < NB; b++) {
                    float4 h = *(const float4*)&hsp[b][(wsg << 5) + (i4 << 2)]; // broadcast
                    acc[b] = f2fma(w0, make_float2(h.x, h.y), acc[b]);
                    acc[b] = f2fma(w1, make_float2(h.z, h.w), acc[b]);
                }
            }
        }
#pragma unroll
        for (int b = 0; b < NB; b++) red[wsg][lane][b] = acc[b].x + acc[b].y;
        __syncthreads();

        if (tid < 32 * NB) {
            float ssum = prev;
#pragma unroll
            for (int q = 0; q < 8; q++) ssum += red[q][rr5][b5];
            garr[rr5][b5] = ssum;
        }
        __syncthreads();

        if (tid < 8 * NB) {
            float ig = garr[u8][b8];
            float fg = garr[8 + u8][b8];
            float cg = garr[16 + u8][b8];
            float og = garr[24 + u8][b8];
            float si = fast_sigmoid(ig);
            float sf = fast_sigmoid(fg);
            float so = fast_sigmoid(og);
            cstate = sf * cstate + si * fast_tanh(cg);
            float hv = so * fast_tanh(cstate);
            out[((size_t)t * NB + b8) * DD + dir * HH + hbase + u8] = hv;
            __threadfence();   // release before barrier arrive
        }
        __syncthreads();

        if (s == NT - 1) break;

        if (tid == 0) {
            atomicAdd(&bar[s], 1u);
            while (((volatile unsigned*)bar)[s] < 32u) { }
        }
        __syncthreads();

        // stage h_t of own direction (L2, bypass L1 via volatile); MLP=5
        float h0 = vout[((size_t)t * NB + 0) * DD + dir * HH + tid];
        float h1 = vout[((size_t)t * NB + 1) * DD + dir * HH + tid];
        float h2 = vout[((size_t)t * NB + 2) * DD + dir * HH + tid];
        float h3 = vout[((size_t)t * NB + 3) * DD + dir * HH + tid];
        float h4 = vout[((size_t)t * NB + 4) * DD + dir * HH + tid];
        hsp[0][tid] = h0; hsp[1][tid] = h1; hsp[2][tid] = h2;
        hsp[3][tid] = h3; hsp[4][tid] = h4;
        __syncthreads();
    }
}

// ---------------- attention + softmax + context ----------------
__global__ void k_attn(const float* __restrict__ cs, float* __restrict__ outp) {
    __shared__ __align__(16) float css[DD];
    __shared__ float aw[NT];
    __shared__ float r1[NT];
    int b = blockIdx.x, tid = threadIdx.x;
    ((float4*)css)[tid] = ((const float4*)cs)[tid];
    __syncthreads();

    const float4* lb = (const float4*)(g_lout + ((size_t)tid * NB + b) * DD);
    float att = 0.f;
#pragma unroll 4
    for (int i = 0; i < DD / 4; i++) {
        float4 x = lb[i];
        float4 c = ((float4*)css)[i];
        att += x.x * c.x + x.y * c.y + x.z * c.z + x.w * c.w;
    }
    r1[tid] = att;
    __syncthreads();
    for (int st = 64; st > 0; st >>= 1) {
        if (tid < st) r1[tid] = fmaxf(r1[tid], r1[tid + st]);
        __syncthreads();
    }
    float mx = r1[0];
    __syncthreads();
    float e = expf(att - mx);
    r1[tid] = e;
    __syncthreads();
    for (int st = 64; st > 0; st >>= 1) {
        if (tid < st) r1[tid] += r1[tid + st];
        __syncthreads();
    }
    float inv = 1.f / r1[0];
    __syncthreads();
    aw[tid] = e * inv;
    __syncthreads();

    float4 ctx = make_float4(0.f, 0.f, 0.f, 0.f);
    for (int l = 0; l < NT; l++) {
        float wv = aw[l];
        float4 x = *(const float4*)(g_lout + ((size_t)l * NB + b) * DD + (tid << 2));
        ctx.x += wv * x.x; ctx.y += wv * x.y; ctx.z += wv * x.z; ctx.w += wv * x.w;
    }
    *(float4*)(outp + (size_t)b * DD + (tid << 2)) = ctx;
}

// ---------------- launcher ----------------
extern "C" void kernel_launch(void* const* d_in, const int* in_sizes, int n_in,
                              void* d_out, int out_size) {
    const float* episodes = (const float*)d_in[0];
    const float* query    = (const float*)d_in[1];
    const float* cstate   = (const float*)d_in[2];
    const float* ages     = (const float*)d_in[3];
    const float* Wq = (const float*)d_in[4];
    const float* bq = (const float*)d_in[5];
    const float* Wk = (const float*)d_in[6];
    const float* bk = (const float*)d_in[7];
    const float* w_ih_l0  = (const float*)d_in[8];
    const float* w_hh_l0  = (const float*)d_in[9];
    const float* b_ih_l0  = (const float*)d_in[10];
    const float* b_hh_l0  = (const float*)d_in[11];
    const float* w_ih_l0r = (const float*)d_in[12];
    const float* w_hh_l0r = (const float*)d_in[13];
    const float* b_ih_l0r = (const float*)d_in[14];
    const float* b_hh_l0r = (const float*)d_in[15];
    const float* w_ih_l1  = (const float*)d_in[16];
    const float* w_hh_l1  = (const float*)d_in[17];
    const float* b_ih_l1  = (const float*)d_in[18];
    const float* b_hh_l1  = (const float*)d_in[19];
    const float* w_ih_l1r = (const float*)d_in[20];
    const float* w_hh_l1r = (const float*)d_in[21];
    const float* b_ih_l1r = (const float*)d_in[22];
    const float* b_hh_l1r = (const float*)d_in[23];
    float* out = (float*)d_out;

    k_zero  <<<1, 512>>>();
    k_prep  <<<1, 512>>>(query, Wq, bq, Wk, bk);
    k_scores<<<NEP, 256>>>(episodes);
    k_topk  <<<1, 1024>>>(ages);
    k_gather<<<dim3(NT, NB), 128>>>(episodes);

    k_gemm<<<dim3(16, 10, 2), 256>>>(0, w_ih_l0, b_ih_l0, b_hh_l0,
                                        w_ih_l0r, b_ih_l0r, b_hh_l0r);
    k_scan<<<SCTA, 256>>>(0, w_hh_l0, w_hh_l0r);

    k_gemm<<<dim3(16, 10, 2), 256>>>(1, w_ih_l1, b_ih_l1, b_hh_l1,
                                        w_ih_l1r, b_ih_l1r, b_hh_l1r);
    k_scan<<<SCTA, 256>>>(1, w_hh_l1, w_hh_l1r);

    k_attn<<<NB, 128>>>(cstate, out);
}

// round 9
// speedup vs baseline: 1.1505x; 1.0001x over previous
#include <cuda_runtime.h>
#include <math.h>

#define DD    512
#define HH    256
#define G4    1024
#define NT    128
#define NB    5
#define NEP   1024
#define M640  640      // NT*NB
#define SCTA  64       // scan CTAs (32 per direction)

// ---------- static device scratch (no allocation) ----------
__device__ __align__(16) float g_v[DD];
__device__ float g_c0;
__device__ __align__(16) float g_scores[NEP];
__device__ int   g_idx[8];
__device__ float g_wsel[8];
__device__ __align__(16) float g_x0 [M640 * DD];       // scaled selected episodes [t][b][d]
__device__ __align__(16) float g_x1 [M640 * DD];       // layer-0 output
__device__ __align__(16) float g_lout[M640 * DD];      // layer-1 output
__device__ __align__(16) float g_pre[2 * M640 * G4];   // pre-gates [dir][m][j]
__device__ unsigned g_bar[512];                        // [phase][dir][step]

// ---------- packed fp32x2 FMA (Blackwell FFMA2, PTX-only) ----------
union F2U { float2 f; unsigned long long u; };
__device__ __forceinline__ float2 f2fma(float2 a, float2 b, float2 c) {
    F2U A, B, C, Dv; A.f = a; B.f = b; C.f = c;
    asm("fma.rn.f32x2 %0, %1, %2, %3;" : "=l"(Dv.u) : "l"(A.u), "l"(B.u), "l"(C.u));
    return Dv.f;
}

__device__ __forceinline__ float fast_tanh(float x) {
    float r;
    asm("tanh.approx.f32 %0, %1;" : "=f"(r) : "f"(x));
    return r;
}
__device__ __forceinline__ float fast_sigmoid(float x) {
    return __fdividef(1.f, 1.f + __expf(-x));
}

// ---------------- zero barriers ----------------
__global__ void k_zero() {
    int i = threadIdx.x;
    if (i < 512) g_bar[i] = 0u;
}

// ---------------- qp = Wq@q + bq ; v = Wk^T@qp ; c0 = bk.qp ----------------
__global__ void k_prep(const float* __restrict__ query, const float* __restrict__ Wq,
                       const float* __restrict__ bq, const float* __restrict__ Wk,
                       const float* __restrict__ bk) {
    __shared__ float qs[DD], qps[DD], red[DD];
    int tid = threadIdx.x;
    qs[tid] = query[tid];
    __syncthreads();
    const float* wr = Wq + (size_t)tid * DD;
    float s = bq[tid];
#pragma unroll 8
    for (int d = 0; d < DD; d++) s += wr[d] * qs[d];
    qps[tid] = s;
    __syncthreads();
    float vv = 0.f;
#pragma unroll 8
    for (int e = 0; e < DD; e++) vv += Wk[(size_t)e * DD + tid] * qps[e];
    g_v[tid] = vv;
    red[tid] = bk[tid] * qps[tid];
    __syncthreads();
    for (int st = 256; st > 0; st >>= 1) {
        if (tid < st) red[tid] += red[tid + st];
        __syncthreads();
    }
    if (tid == 0) g_c0 = red[0];
}

// ---------------- scores[n] = mean_l(ep[n][l]) . v + c0 ----------------
__global__ void k_scores(const float* __restrict__ ep) {
    __shared__ float4 vs[DD / 4];
    __shared__ float sred[256];
    int tid = threadIdx.x;
    if (tid < 128) vs[tid] = ((const float4*)g_v)[tid];
    __syncthreads();
    const float4* e4 = (const float4*)ep + (size_t)blockIdx.x * (NT * DD / 4);
    float acc = 0.f;
#pragma unroll 4
    for (int it = 0; it < 64; it++) {
        int i = tid + 256 * it;
        float4 x = e4[i];
        float4 w = vs[i & 127];
        acc += x.x * w.x + x.y * w.y + x.z * w.z + x.w * w.w;
    }
    sred[tid] = acc;
    __syncthreads();
    for (int st = 128; st > 0; st >>= 1) {
        if (tid < st) sred[tid] += sred[tid + st];
        __syncthreads();
    }
    if (tid == 0) g_scores[blockIdx.x] = sred[0] * (1.0f / NT) + g_c0;
}

// ---------------- iterative top-5 (1024 threads, 1 elem each) ----------------
__global__ void __launch_bounds__(1024) k_topk(const float* __restrict__ ages) {
    __shared__ float sc[NEP];
    __shared__ float rv[1024];
    __shared__ int   ri[1024];
    int tid = threadIdx.x;
    sc[tid] = g_scores[tid];
    __syncthreads();
    for (int r = 0; r < NB; r++) {
        rv[tid] = sc[tid]; ri[tid] = tid;
        __syncthreads();
        for (int st = 512; st > 0; st >>= 1) {
            if (tid < st) {
                float ov = rv[tid + st]; int oi = ri[tid + st];
                if (ov > rv[tid] || (ov == rv[tid] && oi < ri[tid])) { rv[tid] = ov; ri[tid] = oi; }
            }
            __syncthreads();
        }
        if (tid == 0) {
            g_idx[r]  = ri[0];
            g_wsel[r] = 1.f / (1.f + ages[ri[0]] * 0.01f);
            sc[ri[0]] = -INFINITY;
        }
        __syncthreads();
    }
}

// ---------------- x0[t][b][d] = ep[idx[b]][t][d] * w[b] ----------------
__global__ void k_gather(const float* __restrict__ ep) {
    int t = blockIdx.x, b = blockIdx.y, tid = threadIdx.x;
    int n = g_idx[b];
    float wv = g_wsel[b];
    const float4* src = (const float4*)(ep + ((size_t)n * NT + t) * DD);
    float4* dst = (float4*)(g_x0 + ((size_t)t * NB + b) * DD);
    float4 x = src[tid];
    x.x *= wv; x.y *= wv; x.z *= wv; x.w *= wv;
    dst[tid] = x;
}

// ---------------- pre[dir][m][j] = X[m].Wih[j] + bi[j] + bh[j] ----------------
// grid (16 nt, 10 mt, 2 dir) x 256, 64x64x16 tiles
__global__ void __launch_bounds__(256) k_gemm(int phase,
        const float* __restrict__ B0, const float* __restrict__ bi0, const float* __restrict__ bh0,
        const float* __restrict__ B1, const float* __restrict__ bi1, const float* __restrict__ bh1) {
    const float* A = phase ? g_x1 : g_x0;
    int dir = blockIdx.z;
    const float* B  = dir ? B1  : B0;
    const float* bi = dir ? bi1 : bi0;
    const float* bh = dir ? bh1 : bh0;
    float* C = g_pre + (size_t)dir * M640 * G4;

    __shared__ __align__(16) float As[16][68];
    __shared__ __align__(16) float Bs[16][68];

    int tid = threadIdx.x;
    int m0 = blockIdx.y * 64, n0 = blockIdx.x * 64;
    int tx = tid & 15, ty = tid >> 4;
    float acc[4][4];
#pragma unroll
    for (int i = 0; i < 4; i++)
#pragma unroll
        for (int j = 0; j < 4; j++) acc[i][j] = 0.f;

    int ml = tid >> 2, kl = (tid & 3) << 2;
    const float* Ag = A + (size_t)(m0 + ml) * DD + kl;
    const float* Bg = B + (size_t)(n0 + ml) * DD + kl;

    for (int k0 = 0; k0 < DD; k0 += 16) {
        float4 av = *(const float4*)(Ag + k0);
        float4 bv = *(const float4*)(Bg + k0);
        As[kl + 0][ml] = av.x; As[kl + 1][ml] = av.y; As[kl + 2][ml] = av.z; As[kl + 3][ml] = av.w;
        Bs[kl + 0][ml] = bv.x; Bs[kl + 1][ml] = bv.y; Bs[kl + 2][ml] = bv.z; Bs[kl + 3][ml] = bv.w;
        __syncthreads();
#pragma unroll
        for (int kk = 0; kk < 16; kk++) {
            float4 a = *(const float4*)&As[kk][ty << 2];
            float4 b = *(const float4*)&Bs[kk][tx << 2];
            float aa[4] = { a.x, a.y, a.z, a.w };
            float bb[4] = { b.x, b.y, b.z, b.w };
#pragma unroll
            for (int i = 0; i < 4; i++)
#pragma unroll
                for (int j = 0; j < 4; j++) acc[i][j] += aa[i] * bb[j];
        }
        __syncthreads();
    }
#pragma unroll
    for (int i = 0; i < 4; i++) {
        int m = m0 + (ty << 2) + i;
        int n = n0 + (tx << 2);
        float4 o;
        o.x = acc[i][0] + bi[n + 0] + bh[n + 0];
        o.y = acc[i][1] + bi[n + 1] + bh[n + 1];
        o.z = acc[i][2] + bi[n + 2] + bh[n + 2];
        o.w = acc[i][3] + bi[n + 3] + bh[n + 3];
        *(float4*)&C[(size_t)m * G4 + n] = o;
    }
}

// ---------------- bidirectional LSTM scan (one layer phase) ----------------
// 64 persistent CTAs x 256 thr; CTA owns 8 hidden units (32 gate rows).
// NEW layout: warp = h-segment (broadcast h reads), lane = gate row,
// w_hh slice in registers, f32x2 FMA, approx activations.
__global__ void __launch_bounds__(256) k_scan(int phase,
        const float* __restrict__ whf, const float* __restrict__ whb) {
    float* out = phase ? g_lout : g_x1;
    int cta = blockIdx.x;
    int dir = cta >> 5;
    int gidx = cta & 31;
    int hbase = gidx * 8;
    const float* whh  = dir ? whb : whf;
    const float* preb = g_pre + (size_t)dir * M640 * G4;
    unsigned* bar = g_bar + (phase * 2 + dir) * 128;

    int tid  = threadIdx.x;
    int wsg  = tid >> 5;     // h-segment 0..7: elements [wsg*32, wsg*32+32)
    int lane = tid & 31;     // gate row 0..31
    int jrow = (lane >> 3) * HH + hbase + (lane & 7);

    // weights into registers: this thread's 32 w_hh values as 16 float2
    float2 wreg[16];
    {
        const float2* wr = (const float2*)(whh + (size_t)jrow * HH + wsg * 32);
#pragma unroll
        for (int i = 0; i < 16; i++) wreg[i] = wr[i];
    }

    __shared__ __align__(16) float hsp[NB][HH];  // staged h_{t-1}
    __shared__ float red [8][32][NB];            // per-segment partials
    __shared__ float garr[32][NB];               // reduced gate pre-acts

    int rr5 = tid / NB, b5 = tid - rr5 * NB;              // reduce role (tid<160)
    int jred = (rr5 >> 3) * HH + hbase + (rr5 & 7);
    int u8 = tid / NB, b8 = tid - u8 * NB;                // activation role (tid<40)
    float cstate = 0.f;
    volatile const float* vout = out;

    for (int s = 0; s < NT; s++) {
        int t = dir ? (NT - 1 - s) : s;

        // prefetch pre-gate for this step (overlaps matvec)
        float prev = 0.f;
        if (tid < 32 * NB) prev = __ldg(&preb[((size_t)t * NB + b5) * G4 + jred]);

        float2 acc[NB];
#pragma unroll
        for (int b = 0; b < NB; b++) acc[b] = make_float2(0.f, 0.f);
        if (s > 0) {
#pragma unroll
            for (int i4 = 0; i4 < 8; i4++) {
                float2 w0 = wreg[2 * i4], w1 = wreg[2 * i4 + 1];
#pragma unroll
                for (int b = 0; b < NB; b++) {
                    float4 h = *(const float4*)&hsp[b][(wsg << 5) + (i4 << 2)]; // broadcast
                    acc[b] = f2fma(w0, make_float2(h.x, h.y), acc[b]);
                    acc[b] = f2fma(w1, make_float2(h.z, h.w), acc[b]);
                }
            }
        }
#pragma unroll
        for (int b = 0; b < NB; b++) red[wsg][lane][b] = acc[b].x + acc[b].y;
        __syncthreads();

        if (tid < 32 * NB) {
            float ssum = prev;
#pragma unroll
            for (int q = 0; q < 8; q++) ssum += red[q][rr5][b5];
            garr[rr5][b5] = ssum;
        }
        __syncthreads();

        if (tid < 8 * NB) {
            float ig = garr[u8][b8];
            float fg = garr[8 + u8][b8];
            float cg = garr[16 + u8][b8];
            float og = garr[24 + u8][b8];
            float si = fast_sigmoid(ig);
            float sf = fast_sigmoid(fg);
            float so = fast_sigmoid(og);
            cstate = sf * cstate + si * fast_tanh(cg);
            float hv = so * fast_tanh(cstate);
            out[((size_t)t * NB + b8) * DD + dir * HH + hbase + u8] = hv;
            __threadfence();   // release before barrier arrive
        }
        __syncthreads();

        if (s == NT - 1) break;

        if (tid == 0) {
            atomicAdd(&bar[s], 1u);
            while (((volatile unsigned*)bar)[s] < 32u) { }
        }
        __syncthreads();

        // stage h_t of own direction (L2, bypass L1 via volatile); MLP=5
        float h0 = vout[((size_t)t * NB + 0) * DD + dir * HH + tid];
        float h1 = vout[((size_t)t * NB + 1) * DD + dir * HH + tid];
        float h2 = vout[((size_t)t * NB + 2) * DD + dir * HH + tid];
        float h3 = vout[((size_t)t * NB + 3) * DD + dir * HH + tid];
        float h4 = vout[((size_t)t * NB + 4) * DD + dir * HH + tid];
        hsp[0][tid] = h0; hsp[1][tid] = h1; hsp[2][tid] = h2;
        hsp[3][tid] = h3; hsp[4][tid] = h4;
        __syncthreads();
    }
}

// ---------------- attention + softmax + context ----------------
__global__ void k_attn(const float* __restrict__ cs, float* __restrict__ outp) {
    __shared__ __align__(16) float css[DD];
    __shared__ float aw[NT];
    __shared__ float r1[NT];
    int b = blockIdx.x, tid = threadIdx.x;
    ((float4*)css)[tid] = ((const float4*)cs)[tid];
    __syncthreads();

    const float4* lb = (const float4*)(g_lout + ((size_t)tid * NB + b) * DD);
    float att = 0.f;
#pragma unroll 4
    for (int i = 0; i < DD / 4; i++) {
        float4 x = lb[i];
        float4 c = ((float4*)css)[i];
        att += x.x * c.x + x.y * c.y + x.z * c.z + x.w * c.w;
    }
    r1[tid] = att;
    __syncthreads();
    for (int st = 64; st > 0; st >>= 1) {
        if (tid < st) r1[tid] = fmaxf(r1[tid], r1[tid + st]);
        __syncthreads();
    }
    float mx = r1[0];
    __syncthreads();
    float e = expf(att - mx);
    r1[tid] = e;
    __syncthreads();
    for (int st = 64; st > 0; st >>= 1) {
        if (tid < st) r1[tid] += r1[tid + st];
        __syncthreads();
    }
    float inv = 1.f / r1[0];
    __syncthreads();
    aw[tid] = e * inv;
    __syncthreads();

    float4 ctx = make_float4(0.f, 0.f, 0.f, 0.f);
    for (int l = 0; l < NT; l++) {
        float wv = aw[l];
        float4 x = *(const float4*)(g_lout + ((size_t)l * NB + b) * DD + (tid << 2));
        ctx.x += wv * x.x; ctx.y += wv * x.y; ctx.z += wv * x.z; ctx.w += wv * x.w;
    }
    *(float4*)(outp + (size_t)b * DD + (tid << 2)) = ctx;
}

// ---------------- launcher ----------------
extern "C" void kernel_launch(void* const* d_in, const int* in_sizes, int n_in,
                              void* d_out, int out_size) {
    const float* episodes = (const float*)d_in[0];
    const float* query    = (const float*)d_in[1];
    const float* cstate   = (const float*)d_in[2];
    const float* ages     = (const float*)d_in[3];
    const float* Wq = (const float*)d_in[4];
    const float* bq = (const float*)d_in[5];
    const float* Wk = (const float*)d_in[6];
    const float* bk = (const float*)d_in[7];
    const float* w_ih_l0  = (const float*)d_in[8];
    const float* w_hh_l0  = (const float*)d_in[9];
    const float* b_ih_l0  = (const float*)d_in[10];
    const float* b_hh_l0  = (const float*)d_in[11];
    const float* w_ih_l0r = (const float*)d_in[12];
    const float* w_hh_l0r = (const float*)d_in[13];
    const float* b_ih_l0r = (const float*)d_in[14];
    const float* b_hh_l0r = (const float*)d_in[15];
    const float* w_ih_l1  = (const float*)d_in[16];
    const float* w_hh_l1  = (const float*)d_in[17];
    const float* b_ih_l1  = (const float*)d_in[18];
    const float* b_hh_l1  = (const float*)d_in[19];
    const float* w_ih_l1r = (const float*)d_in[20];
    const float* w_hh_l1r = (const float*)d_in[21];
    const float* b_ih_l1r = (const float*)d_in[22];
    const float* b_hh_l1r = (const float*)d_in[23];
    float* out = (float*)d_out;

    k_zero  <<<1, 512>>>();
    k_prep  <<<1, 512>>>(query, Wq, bq, Wk, bk);
    k_scores<<<NEP, 256>>>(episodes);
    k_topk  <<<1, 1024>>>(ages);
    k_gather<<<dim3(NT, NB), 128>>>(episodes);

    k_gemm<<<dim3(16, 10, 2), 256>>>(0, w_ih_l0, b_ih_l0, b_hh_l0,
                                        w_ih_l0r, b_ih_l0r, b_hh_l0r);
    k_scan<<<SCTA, 256>>>(0, w_hh_l0, w_hh_l0r);

    k_gemm<<<dim3(16, 10, 2), 256>>>(1, w_ih_l1, b_ih_l1, b_hh_l1,
                                        w_ih_l1r, b_ih_l1r, b_hh_l1r);
    k_scan<<<SCTA, 256>>>(1, w_hh_l1, w_hh_l1r);

    k_attn<<<NB, 128>>>(cstate, out);
}